// round 17
// baseline (speedup 1.0000x reference)
#include <cuda_runtime.h>

// Problem constants
#define N_IN   1024
#define N_OUT  1024
#define B_TOT  32
#define TPB    256            // threads per block; each thread owns 4 consecutive o's
// R16 profile: occ=20.3% (grid-limited, 256 CTAs), DRAM=47.8% -> latency-bound.
// Fix: double the grid. NCH 32 -> 64 => 512 CTAs, ~3 CTAs/SM at 80 regs.
#define NCH    64             // number of i-chunks
#define CHUNK  (N_IN / NCH)   // 16 i's per chunk
#define BG     4              // batches per block (W reuse; validated by L2=30.6% >> DRAM share)
#define BGRP   (B_TOT / BG)   // 8 batch groups

// Vectorized zero-init of the output (poisoned 0xAA before timing; we
// accumulate into it with atomics).
__global__ void zero_out_kernel(float4* __restrict__ out, int n4) {
    int i = blockIdx.x * blockDim.x + threadIdx.x;
    if (i < n4) out[i] = make_float4(0.f, 0.f, 0.f, 0.f);
}

__global__ __launch_bounds__(TPB)
void synapses_partial_kernel(const float* __restrict__ spikes,
                             const float* __restrict__ mem,
                             const float* __restrict__ rev,
                             const float* __restrict__ syn,
                             const float* __restrict__ W,
                             float* __restrict__ out)
{
    const float decay = 1.0f - 1.0f / 5.0f;   // TAU = 5

    const int ic = blockIdx.x;          // i-chunk index
    const int bg = blockIdx.y;          // batch-group index
    const int i0 = ic * CHUNK;
    const int b0 = bg * BG;
    const int o4 = threadIdx.x;         // float4 index along o; o = 4*o4

    // Preload the per-(b,i) scalars for this chunk into shared memory.
    __shared__ float s_rev[BG][CHUNK];
    __shared__ float s_spk[BG][CHUNK];
    {
        int t = threadIdx.x;
        if (t < BG * CHUNK) {                       // 64 threads load rev
            int b = t / CHUNK, ii = t % CHUNK;
            s_rev[b][ii] = rev[(b0 + b) * N_IN + i0 + ii];
        } else if (t < 2 * BG * CHUNK) {            // next 64 load spikes
            int u = t - BG * CHUNK;
            int b = u / CHUNK, ii = u % CHUNK;
            s_spk[b][ii] = spikes[(b0 + b) * N_IN + i0 + ii];
        }
    }
    __syncthreads();

    float4 a1[BG];   // sum_i u * rev
    float4 a2[BG];   // sum_i u
#pragma unroll
    for (int b = 0; b < BG; b++) {
        a1[b] = make_float4(0.f, 0.f, 0.f, 0.f);
        a2[b] = make_float4(0.f, 0.f, 0.f, 0.f);
    }

    const float4* __restrict__ Wv = reinterpret_cast<const float4*>(W);
    const float4* __restrict__ Sv = reinterpret_cast<const float4*>(syn);
    const int row4 = N_OUT / 4;   // float4's per row = 256

#pragma unroll 2
    for (int ii = 0; ii < CHUNK; ii++) {
        const int i = i0 + ii;
        // Batch loads first; with 2x the warps chip-wide (512 CTAs) the
        // aggregate in-flight bytes should now exceed the ~2.5MB BW*latency
        // product that 47.8% DRAM said we were missing.
        const float4 w = __ldg(&Wv[i * row4 + o4]);
        float4 s[BG];
#pragma unroll
        for (int b = 0; b < BG; b++) {
            // syn is a pure 128MB stream: evict-first keeps W L2-resident.
            s[b] = __ldcs(&Sv[((b0 + b) * N_IN + i) * row4 + o4]);
        }
#pragma unroll
        for (int b = 0; b < BG; b++) {
            const float spk = s_spk[b][ii];
            const float rv  = s_rev[b][ii];

            const float ux = fmaf(s[b].x, decay, spk) * w.x;
            const float uy = fmaf(s[b].y, decay, spk) * w.y;
            const float uz = fmaf(s[b].z, decay, spk) * w.z;
            const float uw = fmaf(s[b].w, decay, spk) * w.w;

            a1[b].x = fmaf(ux, rv, a1[b].x);  a2[b].x += ux;
            a1[b].y = fmaf(uy, rv, a1[b].y);  a2[b].y += uy;
            a1[b].z = fmaf(uz, rv, a1[b].z);  a2[b].z += uz;
            a1[b].w = fmaf(uw, rv, a1[b].w);  a2[b].w += uw;
        }
    }

    // Per-chunk contribution: a1 - mem*a2, accumulated with REDG atomics
    // (2M ops spread over 32K addresses -> parallel across LTS partitions).
    // Validation is rel_err < 1e-3; fp32 atomic-order variance ~1e-7 -> safe.
#pragma unroll
    for (int b = 0; b < BG; b++) {
        const int base = (b0 + b) * N_OUT + 4 * o4;
        const float4 m = *reinterpret_cast<const float4*>(&mem[base]);
        float* op = &out[base];
        atomicAdd(op + 0, a1[b].x - m.x * a2[b].x);
        atomicAdd(op + 1, a1[b].y - m.y * a2[b].y);
        atomicAdd(op + 2, a1[b].z - m.z * a2[b].z);
        atomicAdd(op + 3, a1[b].w - m.w * a2[b].w);
    }
}

extern "C" void kernel_launch(void* const* d_in, const int* in_sizes, int n_in,
                              void* d_out, int out_size)
{
    // Identify tensors: syn and weights by unique sizes, the three [B, N]
    // tensors by declaration order (in_spikes, mem, rev).
    const float* spikes = nullptr;
    const float* mem    = nullptr;
    const float* rev    = nullptr;
    const float* syn    = nullptr;
    const float* W      = nullptr;

    int small_seen = 0;
    for (int i = 0; i < n_in; i++) {
        const float* p = (const float*)d_in[i];
        if (in_sizes[i] == B_TOT * N_IN * N_OUT) {
            syn = p;
        } else if (in_sizes[i] == N_IN * N_OUT) {
            W = p;
        } else {  // 32768-element tensors in order: in_spikes, mem, rev
            if      (small_seen == 0) spikes = p;
            else if (small_seen == 1) mem    = p;
            else                      rev    = p;
            small_seen++;
        }
    }

    float* out = (float*)d_out;
    const int n4 = out_size / 4;   // 8192 float4's

    // Period-2 sequence [zero, MAIN]: ncu's "-s 5 -c 1" lands on MAIN (odd
    // position), confirmed by the R16 capture.
    zero_out_kernel<<<(n4 + TPB - 1) / TPB, TPB>>>(reinterpret_cast<float4*>(out), n4);

    dim3 grid(NCH, BGRP);   // 64 x 8 = 512 blocks (~3/SM resident)
    synapses_partial_kernel<<<grid, TPB>>>(spikes, mem, rev, syn, W, out);
}